// round 5
// baseline (speedup 1.0000x reference)
#include <cuda_runtime.h>
#include <cuda_bf16.h>
#include <float.h>
#include <math.h>

// ---------------------------------------------------------------------------
// MEATransformer: top-3 retrieval over 500K cosine sims + tiny 2-layer
// transformer (768 seqs x 3 tokens x 256) + logits/retrieval mix.
// Round 3: retrieval path unchanged; tail rewritten as dumb-correct kernels.
// ---------------------------------------------------------------------------

#define NN       500000
#define DD       256
#define BB       256
#define KK       3
#define NLAB     12
#define CT       128            // columns per tile in sims kernel
#define NTILES   3907           // ceil(500000/128)
#define GX       128            // sims gridDim.x (partials width)
#define NSEQ     768            // B*K
#define MROWS    2304           // NSEQ*3 token rows

// ---------------- device scratch (no cudaMalloc allowed) -------------------
__device__ float g_qn   [BB * DD];
__device__ float g_pv   [BB * GX * 3];
__device__ int   g_pi   [BB * GX * 3];
__device__ float g_score[NSEQ];
__device__ int   g_idx  [NSEQ];
__device__ int   g_lab  [NSEQ];
__device__ float g_H    [MROWS * DD];
__device__ float g_Qb   [MROWS * DD];
__device__ float g_Kb   [MROWS * DD];
__device__ float g_Vb   [MROWS * DD];
__device__ float g_Ab   [MROWS * DD];
__device__ float g_x    [NSEQ * DD];

// ---------------- f32x2 helpers ---------------------------------------------
__device__ __forceinline__ unsigned long long bcast2(float v) {
    unsigned long long r;
    asm("mov.b64 %0, {%1,%1};" : "=l"(r) : "f"(v));
    return r;
}
__device__ __forceinline__ void unpack2(unsigned long long v, float& lo, float& hi) {
    asm("mov.b64 {%0,%1}, %2;" : "=f"(lo), "=f"(hi) : "l"(v));
}
__device__ __forceinline__ void ffma2(unsigned long long& d,
                                      unsigned long long a,
                                      unsigned long long b) {
    asm("fma.rn.f32x2 %0, %1, %2, %0;" : "+l"(d) : "l"(a), "l"(b));
}

// ---------------- top-3 helpers ----------------------------------------------
__device__ __forceinline__ bool better(float v1, int i1, float v2, int i2) {
    return (v1 > v2) || (v1 == v2 && i1 < i2);   // jax top_k: ties -> lower idx
}
__device__ __forceinline__ void ins3(float v, int i,
                                     float& v0, int& i0,
                                     float& v1, int& i1,
                                     float& v2, int& i2) {
    if (better(v, i, v2, i2)) {
        if (better(v, i, v1, i1)) {
            v2 = v1; i2 = i1;
            if (better(v, i, v0, i0)) { v1 = v0; i1 = i0; v0 = v; i0 = i; }
            else                      { v1 = v;  i1 = i; }
        } else { v2 = v; i2 = i; }
    }
}
__device__ __forceinline__ void merge3(float& a0, int& x0, float& a1, int& x1,
                                       float& a2, int& x2,
                                       float b0, int y0, float b1, int y1,
                                       float b2, int y2) {
    float o0, o1, o2; int p0, p1, p2;
    if (better(a0, x0, b0, y0)) { o0 = a0; p0 = x0; a0 = a1; x0 = x1; a1 = a2; x1 = x2; a2 = -FLT_MAX; x2 = 0x7fffffff; }
    else                        { o0 = b0; p0 = y0; b0 = b1; y0 = y1; b1 = b2; y1 = y2; b2 = -FLT_MAX; y2 = 0x7fffffff; }
    if (better(a0, x0, b0, y0)) { o1 = a0; p1 = x0; a0 = a1; x0 = x1; }
    else                        { o1 = b0; p1 = y0; b0 = b1; y0 = y1; }
    if (better(a0, x0, b0, y0)) { o2 = a0; p2 = x0; }
    else                        { o2 = b0; p2 = y0; }
    a0 = o0; x0 = p0; a1 = o1; x1 = p1; a2 = o2; x2 = p2;
}

// ---------------- kernel 1: normalize queries -------------------------------
__global__ void normalize_kernel(const float* __restrict__ q) {
    __shared__ float ws[8];
    int b = blockIdx.x, t = threadIdx.x;
    float v = q[b * DD + t];
    float s = v * v;
    #pragma unroll
    for (int o = 16; o; o >>= 1) s += __shfl_xor_sync(0xffffffffu, s, o);
    if ((t & 31) == 0) ws[t >> 5] = s;
    __syncthreads();
    float tot = 0.f;
    #pragma unroll
    for (int w = 0; w < 8; w++) tot += ws[w];
    g_qn[b * DD + t] = v / sqrtf(tot);
}

// ---------------- kernel 2: sims GEMM fused with streaming top-3 ------------
__global__ void __launch_bounds__(256, 2)
sims_topk_kernel(const float* __restrict__ w) {
    __shared__ float qs[64][33];
    __shared__ float wsm[32][CT];

    const int tid = threadIdx.x;
    const int tx = tid & 15, ty = tid >> 4;
    const int qrow0 = blockIdx.y * 64;

    float tv[4][3]; int ti[4][3];
    #pragma unroll
    for (int r = 0; r < 4; r++)
        #pragma unroll
        for (int j = 0; j < 3; j++) { tv[r][j] = -FLT_MAX; ti[r][j] = 0x7fffffff; }

    for (int t = blockIdx.x; t < NTILES; t += GX) {
        const int col0 = t * CT;
        unsigned long long acc[4][4];
        #pragma unroll
        for (int r = 0; r < 4; r++)
            #pragma unroll
            for (int p = 0; p < 4; p++) acc[r][p] = 0ull;

        for (int dk = 0; dk < 8; dk++) {
            #pragma unroll
            for (int j = 0; j < 8; j++) {
                int lin = tid + j * 256;
                int r = lin >> 5, c = lin & 31;
                qs[r][c] = g_qn[(qrow0 + r) * DD + dk * 32 + c];
            }
            #pragma unroll
            for (int j = 0; j < 16; j++) {
                int lin = tid + j * 256;
                int r = lin >> 7, c = lin & 127;
                int col = col0 + c;
                wsm[r][c] = (col < NN) ? w[(dk * 32 + r) * NN + col] : 0.f;
            }
            __syncthreads();
            #pragma unroll
            for (int d = 0; d < 32; d++) {
                const ulonglong2* wp = (const ulonglong2*)&wsm[d][tx * 8];
                ulonglong2 wA = wp[0];
                ulonglong2 wB = wp[1];
                #pragma unroll
                for (int rr = 0; rr < 4; rr++) {
                    unsigned long long qv = bcast2(qs[ty * 4 + rr][d]);
                    ffma2(acc[rr][0], qv, wA.x);
                    ffma2(acc[rr][1], qv, wA.y);
                    ffma2(acc[rr][2], qv, wB.x);
                    ffma2(acc[rr][3], qv, wB.y);
                }
            }
            __syncthreads();
        }
        #pragma unroll
        for (int rr = 0; rr < 4; rr++) {
            #pragma unroll
            for (int p = 0; p < 4; p++) {
                float lo, hi;
                unpack2(acc[rr][p], lo, hi);
                int c0 = col0 + tx * 8 + p * 2;
                if (c0 < NN)
                    ins3(lo, c0, tv[rr][0], ti[rr][0], tv[rr][1], ti[rr][1], tv[rr][2], ti[rr][2]);
                if (c0 + 1 < NN)
                    ins3(hi, c0 + 1, tv[rr][0], ti[rr][0], tv[rr][1], ti[rr][1], tv[rr][2], ti[rr][2]);
            }
        }
    }

    #pragma unroll
    for (int rr = 0; rr < 4; rr++) {
        #pragma unroll
        for (int off = 8; off >= 1; off >>= 1) {
            float b0 = __shfl_xor_sync(0xffffffffu, tv[rr][0], off, 16);
            float b1 = __shfl_xor_sync(0xffffffffu, tv[rr][1], off, 16);
            float b2 = __shfl_xor_sync(0xffffffffu, tv[rr][2], off, 16);
            int   y0 = __shfl_xor_sync(0xffffffffu, ti[rr][0], off, 16);
            int   y1 = __shfl_xor_sync(0xffffffffu, ti[rr][1], off, 16);
            int   y2 = __shfl_xor_sync(0xffffffffu, ti[rr][2], off, 16);
            merge3(tv[rr][0], ti[rr][0], tv[rr][1], ti[rr][1], tv[rr][2], ti[rr][2],
                   b0, y0, b1, y1, b2, y2);
        }
        if (tx == 0) {
            int q = qrow0 + ty * 4 + rr;
            int base = (q * GX + blockIdx.x) * 3;
            #pragma unroll
            for (int j = 0; j < 3; j++) { g_pv[base + j] = tv[rr][j]; g_pi[base + j] = ti[rr][j]; }
        }
    }
}

// ---------------- kernel 3: merge partial top-3 per query -------------------
__global__ void topk_merge_kernel(const int* __restrict__ label) {
    __shared__ float sv[4][3];
    __shared__ int   si[4][3];
    int b = blockIdx.x, t = threadIdx.x;
    int base = (b * GX + t) * 3;
    float v0 = g_pv[base], v1 = g_pv[base + 1], v2 = g_pv[base + 2];
    int   i0 = g_pi[base], i1 = g_pi[base + 1], i2 = g_pi[base + 2];
    #pragma unroll
    for (int off = 16; off >= 1; off >>= 1) {
        float b0 = __shfl_xor_sync(0xffffffffu, v0, off);
        float b1 = __shfl_xor_sync(0xffffffffu, v1, off);
        float b2 = __shfl_xor_sync(0xffffffffu, v2, off);
        int   y0 = __shfl_xor_sync(0xffffffffu, i0, off);
        int   y1 = __shfl_xor_sync(0xffffffffu, i1, off);
        int   y2 = __shfl_xor_sync(0xffffffffu, i2, off);
        merge3(v0, i0, v1, i1, v2, i2, b0, y0, b1, y1, b2, y2);
    }
    int warp = t >> 5;
    if ((t & 31) == 0) { sv[warp][0] = v0; si[warp][0] = i0; sv[warp][1] = v1; si[warp][1] = i1; sv[warp][2] = v2; si[warp][2] = i2; }
    __syncthreads();
    if (t == 0) {
        float f0 = -FLT_MAX, f1 = -FLT_MAX, f2 = -FLT_MAX;
        int   j0 = 0x7fffffff, j1 = 0x7fffffff, j2 = 0x7fffffff;
        for (int wp = 0; wp < 4; wp++)
            for (int e = 0; e < 3; e++)
                ins3(sv[wp][e], si[wp][e], f0, j0, f1, j1, f2, j2);
        float fv[3] = {f0, f1, f2}; int fi[3] = {j0, j1, j2};
        for (int k = 0; k < 3; k++) {
            g_score[b * 3 + k] = fv[k];
            g_idx[b * 3 + k]   = fi[k];
            g_lab[b * 3 + k]   = label[fi[k]];
        }
    }
}

// ---------------- kernel 4: build H (gather) ---------------------------------
__global__ void build_h_kernel(const float* __restrict__ queries,
                               const float* __restrict__ w) {
    int s = blockIdx.x;       // 0..767
    int d = threadIdx.x;      // 0..255
    int b = s / KK;
    int lab = g_lab[s];
    float score = g_score[s];
    int idx = g_idx[s];
    float* Hrow = &g_H[s * 3 * DD];
    Hrow[d]           = (d == lab) ? score : 0.f;   // CLS token
    Hrow[DD + d]      = queries[b * DD + d];        // query token
    Hrow[2 * DD + d]  = w[d * NN + idx];            // retrieved token
}

// ---------------- dumb tail: fused Q/K/V matvec, 8 rows per block -----------
__global__ void qkv_kernel(const float* __restrict__ Wq, const float* __restrict__ bq,
                           const float* __restrict__ Wk, const float* __restrict__ bk,
                           const float* __restrict__ Wv, const float* __restrict__ bv) {
    __shared__ float h[8][DD];
    int r0 = blockIdx.x * 8, t = threadIdx.x;
    #pragma unroll
    for (int i = 0; i < 8; i++) h[i][t] = g_H[(r0 + i) * DD + t];
    __syncthreads();
    float aq[8], ak[8], av[8];
    #pragma unroll
    for (int i = 0; i < 8; i++) { aq[i] = bq[t]; ak[i] = bk[t]; av[i] = bv[t]; }
    for (int d = 0; d < DD; d++) {
        float wq = Wq[d * DD + t], wk = Wk[d * DD + t], wv = Wv[d * DD + t];
        #pragma unroll
        for (int i = 0; i < 8; i++) {
            float hv = h[i][d];
            aq[i] += hv * wq;
            ak[i] += hv * wk;
            av[i] += hv * wv;
        }
    }
    #pragma unroll
    for (int i = 0; i < 8; i++) {
        g_Qb[(r0 + i) * DD + t] = aq[i];
        g_Kb[(r0 + i) * DD + t] = ak[i];
        g_Vb[(r0 + i) * DD + t] = av[i];
    }
}

// ---------------- dumb attention: scalar 3x3 per sequence --------------------
__global__ void attn_kernel() {
    __shared__ float q[3][DD], k[3][DD], v[3][DD], a[9];
    int s = blockIdx.x, t = threadIdx.x;
    int base = s * 3 * DD;
    #pragma unroll
    for (int i = 0; i < 3; i++) {
        q[i][t] = g_Qb[base + i * DD + t];
        k[i][t] = g_Kb[base + i * DD + t];
        v[i][t] = g_Vb[base + i * DD + t];
    }
    __syncthreads();
    if (t < 9) {
        int i = t / 3, j = t % 3;
        float acc = 0.f;
        for (int d = 0; d < DD; d++) acc += q[i][d] * k[j][d];
        a[t] = acc * 0.125f;           // / sqrt(dk), dk = 64
    }
    __syncthreads();
    if (t < 3) {
        float m0 = fmaxf(a[t*3], fmaxf(a[t*3+1], a[t*3+2]));
        float e0 = expf(a[t*3]   - m0);
        float e1 = expf(a[t*3+1] - m0);
        float e2 = expf(a[t*3+2] - m0);
        float inv = 1.f / (e0 + e1 + e2);
        a[t*3] = e0 * inv; a[t*3+1] = e1 * inv; a[t*3+2] = e2 * inv;
    }
    __syncthreads();
    #pragma unroll
    for (int i = 0; i < 3; i++)
        g_Ab[base + i * DD + t] = a[i*3] * v[0][t] + a[i*3+1] * v[1][t] + a[i*3+2] * v[2][t];
}

// ---------------- dumb O projection: H = Ab @ Wo + bo ------------------------
__global__ void oproj_kernel(const float* __restrict__ Wo, const float* __restrict__ bo) {
    __shared__ float h[8][DD];
    int r0 = blockIdx.x * 8, t = threadIdx.x;
    #pragma unroll
    for (int i = 0; i < 8; i++) h[i][t] = g_Ab[(r0 + i) * DD + t];
    __syncthreads();
    float ao[8];
    #pragma unroll
    for (int i = 0; i < 8; i++) ao[i] = bo[t];
    for (int d = 0; d < DD; d++) {
        float wo = Wo[d * DD + t];
        #pragma unroll
        for (int i = 0; i < 8; i++) ao[i] += h[i][d] * wo;
    }
    #pragma unroll
    for (int i = 0; i < 8; i++) g_H[(r0 + i) * DD + t] = ao[i];
}

// ---------------- dumb dense on CLS rows: x = tanh(H[:,0,:] @ W + b) ---------
__global__ void dense_kernel(const float* __restrict__ W, const float* __restrict__ b) {
    __shared__ float h[DD];
    int s = blockIdx.x, t = threadIdx.x;
    h[t] = g_H[s * 3 * DD + t];       // CLS row
    __syncthreads();
    float acc = b[t];
    for (int d = 0; d < DD; d++) acc += h[d] * W[d * DD + t];
    g_x[s * DD + t] = tanhf(acc);
}

// ---------------- dumb final: logits mean + retrieval mix --------------------
__global__ void final_kernel(const float* __restrict__ out_w,
                             const float* __restrict__ out_b,
                             float* __restrict__ out) {
    __shared__ float lg[36];
    int b = blockIdx.x, t = threadIdx.x;   // 36 threads
    int k = t / NLAB, l = t % NLAB;
    float acc = out_b[l];
    const float* x = &g_x[(b * 3 + k) * DD];
    for (int d = 0; d < DD; d++) acc += x[d] * out_w[d * NLAB + l];
    lg[t] = acc;
    __syncthreads();
    if (t < NLAB) {
        float mean = (lg[t] + lg[NLAB + t] + lg[2 * NLAB + t]) * (1.f / 3.f);
        int l0 = g_lab[b * 3], l1 = g_lab[b * 3 + 1], l2 = g_lab[b * 3 + 2];
        float cnt = (float)((l0 == t) + (l1 == t) + (l2 == t));
        out[b * NLAB + t] = 0.5f * mean + 0.5f * (cnt * (1.f / 3.f));
    }
}

// ---------------- launcher ---------------------------------------------------
extern "C" void kernel_launch(void* const* d_in, const int* in_sizes, int n_in,
                              void* d_out, int out_size) {
    const float* queries = (const float*)d_in[0];
    const float* weight  = (const float*)d_in[1];
    const int*   label   = (const int*)  d_in[2];
    const float* Wq      = (const float*)d_in[3];
    const float* bq      = (const float*)d_in[4];
    const float* Wk      = (const float*)d_in[5];
    const float* bk      = (const float*)d_in[6];
    const float* Wv      = (const float*)d_in[7];
    const float* bv      = (const float*)d_in[8];
    const float* Wo      = (const float*)d_in[9];
    const float* bo      = (const float*)d_in[10];
    const float* dense_w = (const float*)d_in[11];
    const float* dense_b = (const float*)d_in[12];
    const float* out_w   = (const float*)d_in[13];
    const float* out_b   = (const float*)d_in[14];
    float* out = (float*)d_out;

    normalize_kernel<<<BB, DD>>>(queries);
    sims_topk_kernel<<<dim3(GX, 4), 256>>>(weight);
    topk_merge_kernel<<<BB, GX>>>(label);
    build_h_kernel<<<NSEQ, DD>>>(queries, weight);

    for (int l = 0; l < 2; l++) {
        qkv_kernel<<<MROWS / 8, DD>>>(Wq + l * DD * DD, bq + l * DD,
                                      Wk + l * DD * DD, bk + l * DD,
                                      Wv + l * DD * DD, bv + l * DD);
        attn_kernel<<<NSEQ, DD>>>();
        oproj_kernel<<<MROWS / 8, DD>>>(Wo + l * DD * DD, bo + l * DD);
    }
    dense_kernel<<<NSEQ, DD>>>(dense_w, dense_b);
    final_kernel<<<BB, 36>>>(out_w, out_b, out);
}

// round 6
// speedup vs baseline: 1.9318x; 1.9318x over previous
#include <cuda_runtime.h>
#include <cuda_bf16.h>
#include <float.h>
#include <math.h>

// ---------------------------------------------------------------------------
// MEATransformer: top-3 retrieval over 500K cosine sims + tiny 2-layer
// transformer (768 seqs x 3 tokens x 256) + logits/retrieval mix.
// Round 5: fix 4-way smem bank conflicts in sims inner loop (split-column
// LDS.128), GX=148 for exact 2-wave occupancy. Tail unchanged (proven).
// ---------------------------------------------------------------------------

#define NN       500000
#define DD       256
#define BB       256
#define KK       3
#define NLAB     12
#define CT       128            // columns per tile in sims kernel
#define NTILES   3907           // ceil(500000/128)
#define GX       148            // sims gridDim.x (partials width) = 2 exact waves
#define NSEQ     768            // B*K
#define MROWS    2304           // NSEQ*3 token rows

// ---------------- device scratch (no cudaMalloc allowed) -------------------
__device__ float g_qn   [BB * DD];
__device__ float g_pv   [BB * GX * 3];
__device__ int   g_pi   [BB * GX * 3];
__device__ float g_score[NSEQ];
__device__ int   g_idx  [NSEQ];
__device__ int   g_lab  [NSEQ];
__device__ float g_H    [MROWS * DD];
__device__ float g_Qb   [MROWS * DD];
__device__ float g_Kb   [MROWS * DD];
__device__ float g_Vb   [MROWS * DD];
__device__ float g_Ab   [MROWS * DD];
__device__ float g_x    [NSEQ * DD];

// ---------------- f32x2 helpers ---------------------------------------------
__device__ __forceinline__ unsigned long long bcast2(float v) {
    unsigned long long r;
    asm("mov.b64 %0, {%1,%1};" : "=l"(r) : "f"(v));
    return r;
}
__device__ __forceinline__ void unpack2(unsigned long long v, float& lo, float& hi) {
    asm("mov.b64 {%0,%1}, %2;" : "=f"(lo), "=f"(hi) : "l"(v));
}
__device__ __forceinline__ void ffma2(unsigned long long& d,
                                      unsigned long long a,
                                      unsigned long long b) {
    asm("fma.rn.f32x2 %0, %1, %2, %0;" : "+l"(d) : "l"(a), "l"(b));
}

// ---------------- top-3 helpers ----------------------------------------------
__device__ __forceinline__ bool better(float v1, int i1, float v2, int i2) {
    return (v1 > v2) || (v1 == v2 && i1 < i2);   // jax top_k: ties -> lower idx
}
__device__ __forceinline__ void ins3(float v, int i,
                                     float& v0, int& i0,
                                     float& v1, int& i1,
                                     float& v2, int& i2) {
    if (better(v, i, v2, i2)) {
        if (better(v, i, v1, i1)) {
            v2 = v1; i2 = i1;
            if (better(v, i, v0, i0)) { v1 = v0; i1 = i0; v0 = v; i0 = i; }
            else                      { v1 = v;  i1 = i; }
        } else { v2 = v; i2 = i; }
    }
}
__device__ __forceinline__ void merge3(float& a0, int& x0, float& a1, int& x1,
                                       float& a2, int& x2,
                                       float b0, int y0, float b1, int y1,
                                       float b2, int y2) {
    float o0, o1, o2; int p0, p1, p2;
    if (better(a0, x0, b0, y0)) { o0 = a0; p0 = x0; a0 = a1; x0 = x1; a1 = a2; x1 = x2; a2 = -FLT_MAX; x2 = 0x7fffffff; }
    else                        { o0 = b0; p0 = y0; b0 = b1; y0 = y1; b1 = b2; y1 = y2; b2 = -FLT_MAX; y2 = 0x7fffffff; }
    if (better(a0, x0, b0, y0)) { o1 = a0; p1 = x0; a0 = a1; x0 = x1; }
    else                        { o1 = b0; p1 = y0; b0 = b1; y0 = y1; }
    if (better(a0, x0, b0, y0)) { o2 = a0; p2 = x0; }
    else                        { o2 = b0; p2 = y0; }
    a0 = o0; x0 = p0; a1 = o1; x1 = p1; a2 = o2; x2 = p2;
}

// ---------------- kernel 1: normalize queries -------------------------------
__global__ void normalize_kernel(const float* __restrict__ q) {
    __shared__ float ws[8];
    int b = blockIdx.x, t = threadIdx.x;
    float v = q[b * DD + t];
    float s = v * v;
    #pragma unroll
    for (int o = 16; o; o >>= 1) s += __shfl_xor_sync(0xffffffffu, s, o);
    if ((t & 31) == 0) ws[t >> 5] = s;
    __syncthreads();
    float tot = 0.f;
    #pragma unroll
    for (int w = 0; w < 8; w++) tot += ws[w];
    g_qn[b * DD + t] = v / sqrtf(tot);
}

// ---------------- kernel 2: sims GEMM fused with streaming top-3 ------------
// block: 256 threads (16 tx x 16 ty); tile 64 queries x 128 columns;
// micro-tile 4 rows x 8 cols. Each thread owns cols [tx*4, tx*4+4) and
// [64+tx*4, 64+tx*4+4) -> both LDS.128 are contiguous 16B/lane, conflict-free.
__global__ void __launch_bounds__(256, 2)
sims_topk_kernel(const float* __restrict__ w) {
    __shared__ float qs[64][33];
    __shared__ float wsm[32][CT];

    const int tid = threadIdx.x;
    const int tx = tid & 15, ty = tid >> 4;
    const int qrow0 = blockIdx.y * 64;

    float tv[4][3]; int ti[4][3];
    #pragma unroll
    for (int r = 0; r < 4; r++)
        #pragma unroll
        for (int j = 0; j < 3; j++) { tv[r][j] = -FLT_MAX; ti[r][j] = 0x7fffffff; }

    for (int t = blockIdx.x; t < NTILES; t += GX) {
        const int col0 = t * CT;
        unsigned long long acc[4][4];
        #pragma unroll
        for (int r = 0; r < 4; r++)
            #pragma unroll
            for (int p = 0; p < 4; p++) acc[r][p] = 0ull;

        for (int dk = 0; dk < 8; dk++) {
            #pragma unroll
            for (int j = 0; j < 8; j++) {
                int lin = tid + j * 256;
                int r = lin >> 5, c = lin & 31;
                qs[r][c] = g_qn[(qrow0 + r) * DD + dk * 32 + c];
            }
            #pragma unroll
            for (int j = 0; j < 16; j++) {
                int lin = tid + j * 256;
                int r = lin >> 7, c = lin & 127;
                int col = col0 + c;
                wsm[r][c] = (col < NN) ? w[(dk * 32 + r) * NN + col] : 0.f;
            }
            __syncthreads();
            #pragma unroll
            for (int d = 0; d < 32; d++) {
                // conflict-free: lane byte offset = tx*16 (contiguous 16B)
                unsigned long long wA0, wA1, wB0, wB1;
                {
                    const ulonglong2 a = *(const ulonglong2*)&wsm[d][tx * 4];
                    const ulonglong2 b = *(const ulonglong2*)&wsm[d][64 + tx * 4];
                    wA0 = a.x; wA1 = a.y; wB0 = b.x; wB1 = b.y;
                }
                #pragma unroll
                for (int rr = 0; rr < 4; rr++) {
                    unsigned long long qv = bcast2(qs[ty * 4 + rr][d]);
                    ffma2(acc[rr][0], qv, wA0);
                    ffma2(acc[rr][1], qv, wA1);
                    ffma2(acc[rr][2], qv, wB0);
                    ffma2(acc[rr][3], qv, wB1);
                }
            }
            __syncthreads();
        }
        // streaming top-3 insertion
        // acc[rr][0] -> cols col0+tx*4 +0/+1 ; acc[rr][1] -> +2/+3
        // acc[rr][2] -> cols col0+64+tx*4 +0/+1 ; acc[rr][3] -> +2/+3
        #pragma unroll
        for (int rr = 0; rr < 4; rr++) {
            #pragma unroll
            for (int p = 0; p < 4; p++) {
                float lo, hi;
                unpack2(acc[rr][p], lo, hi);
                int grp = p >> 1;                 // 0: first 64 cols, 1: second
                int c0 = col0 + grp * 64 + tx * 4 + (p & 1) * 2;
                if (c0 < NN)
                    ins3(lo, c0, tv[rr][0], ti[rr][0], tv[rr][1], ti[rr][1], tv[rr][2], ti[rr][2]);
                if (c0 + 1 < NN)
                    ins3(hi, c0 + 1, tv[rr][0], ti[rr][0], tv[rr][1], ti[rr][1], tv[rr][2], ti[rr][2]);
            }
        }
    }

    #pragma unroll
    for (int rr = 0; rr < 4; rr++) {
        #pragma unroll
        for (int off = 8; off >= 1; off >>= 1) {
            float b0 = __shfl_xor_sync(0xffffffffu, tv[rr][0], off, 16);
            float b1 = __shfl_xor_sync(0xffffffffu, tv[rr][1], off, 16);
            float b2 = __shfl_xor_sync(0xffffffffu, tv[rr][2], off, 16);
            int   y0 = __shfl_xor_sync(0xffffffffu, ti[rr][0], off, 16);
            int   y1 = __shfl_xor_sync(0xffffffffu, ti[rr][1], off, 16);
            int   y2 = __shfl_xor_sync(0xffffffffu, ti[rr][2], off, 16);
            merge3(tv[rr][0], ti[rr][0], tv[rr][1], ti[rr][1], tv[rr][2], ti[rr][2],
                   b0, y0, b1, y1, b2, y2);
        }
        if (tx == 0) {
            int q = qrow0 + ty * 4 + rr;
            int base = (q * GX + blockIdx.x) * 3;
            #pragma unroll
            for (int j = 0; j < 3; j++) { g_pv[base + j] = tv[rr][j]; g_pi[base + j] = ti[rr][j]; }
        }
    }
}

// ---------------- kernel 3: merge partial top-3 per query -------------------
// 160 threads (5 warps); lanes t >= GX hold neutral values.
__global__ void topk_merge_kernel(const int* __restrict__ label) {
    __shared__ float sv[5][3];
    __shared__ int   si[5][3];
    int b = blockIdx.x, t = threadIdx.x;
    float v0 = -FLT_MAX, v1 = -FLT_MAX, v2 = -FLT_MAX;
    int   i0 = 0x7fffffff, i1 = 0x7fffffff, i2 = 0x7fffffff;
    if (t < GX) {
        int base = (b * GX + t) * 3;
        v0 = g_pv[base];     i0 = g_pi[base];
        v1 = g_pv[base + 1]; i1 = g_pi[base + 1];
        v2 = g_pv[base + 2]; i2 = g_pi[base + 2];
    }
    #pragma unroll
    for (int off = 16; off >= 1; off >>= 1) {
        float b0 = __shfl_xor_sync(0xffffffffu, v0, off);
        float b1 = __shfl_xor_sync(0xffffffffu, v1, off);
        float b2 = __shfl_xor_sync(0xffffffffu, v2, off);
        int   y0 = __shfl_xor_sync(0xffffffffu, i0, off);
        int   y1 = __shfl_xor_sync(0xffffffffu, i1, off);
        int   y2 = __shfl_xor_sync(0xffffffffu, i2, off);
        merge3(v0, i0, v1, i1, v2, i2, b0, y0, b1, y1, b2, y2);
    }
    int warp = t >> 5;
    if ((t & 31) == 0) { sv[warp][0] = v0; si[warp][0] = i0; sv[warp][1] = v1; si[warp][1] = i1; sv[warp][2] = v2; si[warp][2] = i2; }
    __syncthreads();
    if (t == 0) {
        float f0 = -FLT_MAX, f1 = -FLT_MAX, f2 = -FLT_MAX;
        int   j0 = 0x7fffffff, j1 = 0x7fffffff, j2 = 0x7fffffff;
        for (int wp = 0; wp < 5; wp++)
            for (int e = 0; e < 3; e++)
                ins3(sv[wp][e], si[wp][e], f0, j0, f1, j1, f2, j2);
        float fv[3] = {f0, f1, f2}; int fi[3] = {j0, j1, j2};
        for (int k = 0; k < 3; k++) {
            g_score[b * 3 + k] = fv[k];
            g_idx[b * 3 + k]   = fi[k];
            g_lab[b * 3 + k]   = label[fi[k]];
        }
    }
}

// ---------------- kernel 4: build H (gather) ---------------------------------
__global__ void build_h_kernel(const float* __restrict__ queries,
                               const float* __restrict__ w) {
    int s = blockIdx.x;       // 0..767
    int d = threadIdx.x;      // 0..255
    int b = s / KK;
    int lab = g_lab[s];
    float score = g_score[s];
    int idx = g_idx[s];
    float* Hrow = &g_H[s * 3 * DD];
    Hrow[d]           = (d == lab) ? score : 0.f;   // CLS token
    Hrow[DD + d]      = queries[b * DD + d];        // query token
    Hrow[2 * DD + d]  = w[d * NN + idx];            // retrieved token
}

// ---------------- tail: fused Q/K/V matvec, 8 rows per block ----------------
__global__ void qkv_kernel(const float* __restrict__ Wq, const float* __restrict__ bq,
                           const float* __restrict__ Wk, const float* __restrict__ bk,
                           const float* __restrict__ Wv, const float* __restrict__ bv) {
    __shared__ float h[8][DD];
    int r0 = blockIdx.x * 8, t = threadIdx.x;
    #pragma unroll
    for (int i = 0; i < 8; i++) h[i][t] = g_H[(r0 + i) * DD + t];
    __syncthreads();
    float aq[8], ak[8], av[8];
    #pragma unroll
    for (int i = 0; i < 8; i++) { aq[i] = bq[t]; ak[i] = bk[t]; av[i] = bv[t]; }
    for (int d = 0; d < DD; d++) {
        float wq = Wq[d * DD + t], wk = Wk[d * DD + t], wv = Wv[d * DD + t];
        #pragma unroll
        for (int i = 0; i < 8; i++) {
            float hv = h[i][d];
            aq[i] += hv * wq;
            ak[i] += hv * wk;
            av[i] += hv * wv;
        }
    }
    #pragma unroll
    for (int i = 0; i < 8; i++) {
        g_Qb[(r0 + i) * DD + t] = aq[i];
        g_Kb[(r0 + i) * DD + t] = ak[i];
        g_Vb[(r0 + i) * DD + t] = av[i];
    }
}

// ---------------- attention: scalar 3x3 per sequence -------------------------
__global__ void attn_kernel() {
    __shared__ float q[3][DD], k[3][DD], v[3][DD], a[9];
    int s = blockIdx.x, t = threadIdx.x;
    int base = s * 3 * DD;
    #pragma unroll
    for (int i = 0; i < 3; i++) {
        q[i][t] = g_Qb[base + i * DD + t];
        k[i][t] = g_Kb[base + i * DD + t];
        v[i][t] = g_Vb[base + i * DD + t];
    }
    __syncthreads();
    if (t < 9) {
        int i = t / 3, j = t % 3;
        float acc = 0.f;
        for (int d = 0; d < DD; d++) acc += q[i][d] * k[j][d];
        a[t] = acc * 0.125f;           // / sqrt(dk), dk = 64
    }
    __syncthreads();
    if (t < 3) {
        float m0 = fmaxf(a[t*3], fmaxf(a[t*3+1], a[t*3+2]));
        float e0 = expf(a[t*3]   - m0);
        float e1 = expf(a[t*3+1] - m0);
        float e2 = expf(a[t*3+2] - m0);
        float inv = 1.f / (e0 + e1 + e2);
        a[t*3] = e0 * inv; a[t*3+1] = e1 * inv; a[t*3+2] = e2 * inv;
    }
    __syncthreads();
    #pragma unroll
    for (int i = 0; i < 3; i++)
        g_Ab[base + i * DD + t] = a[i*3] * v[0][t] + a[i*3+1] * v[1][t] + a[i*3+2] * v[2][t];
}

// ---------------- O projection: H = Ab @ Wo + bo ------------------------------
__global__ void oproj_kernel(const float* __restrict__ Wo, const float* __restrict__ bo) {
    __shared__ float h[8][DD];
    int r0 = blockIdx.x * 8, t = threadIdx.x;
    #pragma unroll
    for (int i = 0; i < 8; i++) h[i][t] = g_Ab[(r0 + i) * DD + t];
    __syncthreads();
    float ao[8];
    #pragma unroll
    for (int i = 0; i < 8; i++) ao[i] = bo[t];
    for (int d = 0; d < DD; d++) {
        float wo = Wo[d * DD + t];
        #pragma unroll
        for (int i = 0; i < 8; i++) ao[i] += h[i][d] * wo;
    }
    #pragma unroll
    for (int i = 0; i < 8; i++) g_H[(r0 + i) * DD + t] = ao[i];
}

// ---------------- dense on CLS rows: x = tanh(H[:,0,:] @ W + b) --------------
__global__ void dense_kernel(const float* __restrict__ W, const float* __restrict__ b) {
    __shared__ float h[DD];
    int s = blockIdx.x, t = threadIdx.x;
    h[t] = g_H[s * 3 * DD + t];       // CLS row
    __syncthreads();
    float acc = b[t];
    for (int d = 0; d < DD; d++) acc += h[d] * W[d * DD + t];
    g_x[s * DD + t] = tanhf(acc);
}

// ---------------- final: logits mean + retrieval mix -------------------------
__global__ void final_kernel(const float* __restrict__ out_w,
                             const float* __restrict__ out_b,
                             float* __restrict__ out) {
    __shared__ float lg[36];
    int b = blockIdx.x, t = threadIdx.x;   // 36 threads
    int k = t / NLAB, l = t % NLAB;
    float acc = out_b[l];
    const float* x = &g_x[(b * 3 + k) * DD];
    for (int d = 0; d < DD; d++) acc += x[d] * out_w[d * NLAB + l];
    lg[t] = acc;
    __syncthreads();
    if (t < NLAB) {
        float mean = (lg[t] + lg[NLAB + t] + lg[2 * NLAB + t]) * (1.f / 3.f);
        int l0 = g_lab[b * 3], l1 = g_lab[b * 3 + 1], l2 = g_lab[b * 3 + 2];
        float cnt = (float)((l0 == t) + (l1 == t) + (l2 == t));
        out[b * NLAB + t] = 0.5f * mean + 0.5f * (cnt * (1.f / 3.f));
    }
}

// ---------------- launcher ---------------------------------------------------
extern "C" void kernel_launch(void* const* d_in, const int* in_sizes, int n_in,
                              void* d_out, int out_size) {
    const float* queries = (const float*)d_in[0];
    const float* weight  = (const float*)d_in[1];
    const int*   label   = (const int*)  d_in[2];
    const float* Wq      = (const float*)d_in[3];
    const float* bq      = (const float*)d_in[4];
    const float* Wk      = (const float*)d_in[5];
    const float* bk      = (const float*)d_in[6];
    const float* Wv      = (const float*)d_in[7];
    const float* bv      = (const float*)d_in[8];
    const float* Wo      = (const float*)d_in[9];
    const float* bo      = (const float*)d_in[10];
    const float* dense_w = (const float*)d_in[11];
    const float* dense_b = (const float*)d_in[12];
    const float* out_w   = (const float*)d_in[13];
    const float* out_b   = (const float*)d_in[14];
    float* out = (float*)d_out;

    normalize_kernel<<<BB, DD>>>(queries);
    sims_topk_kernel<<<dim3(GX, 4), 256>>>(weight);
    topk_merge_kernel<<<BB, 160>>>(label);
    build_h_kernel<<<NSEQ, DD>>>(queries, weight);

    for (int l = 0; l < 2; l++) {
        qkv_kernel<<<MROWS / 8, DD>>>(Wq + l * DD * DD, bq + l * DD,
                                      Wk + l * DD * DD, bk + l * DD,
                                      Wv + l * DD * DD, bv + l * DD);
        attn_kernel<<<NSEQ, DD>>>();
        oproj_kernel<<<MROWS / 8, DD>>>(Wo + l * DD * DD, bo + l * DD);
    }
    dense_kernel<<<NSEQ, DD>>>(dense_w, dense_b);
    final_kernel<<<BB, 36>>>(out_w, out_b, out);
}